// round 15
// baseline (speedup 1.0000x reference)
#include <cuda_runtime.h>
#include <cuda_bf16.h>
#include <math.h>
#include <stdint.h>

#define T_STEPS 16
#define BATCH   8192
#define IN_F    64
#define HID     256
#define OUT_F   64
#define NCLS    8

// ---- d_out layout (floats), tuple flattened in reference-return order ----
#define SZ_OUTSEQ (T_STEPS*BATCH*NCLS)
#define SZ_HC     (BATCH*HID)
#define SZ_SEQ    (T_STEPS*BATCH*HID)
#define OFF_OUTSEQ 0
#define OFF_HC1   (OFF_OUTSEQ + SZ_OUTSEQ)
#define OFF_HC2   (OFF_HC1 + SZ_HC)
#define OFF_HC3   (OFF_HC2 + SZ_HC)
#define OFF_HC4   (OFF_HC3 + SZ_HC)
#define OFF_I2H   (OFF_HC4 + SZ_HC)
#define OFF_H2H   (OFF_I2H + SZ_SEQ)

#define STEP_CTAS 128

// ---------------- device scratch (no cudaMalloc allowed) ----------------
__device__ __nv_bfloat16 g_ha_hi[2][BATCH * HID];  // h state split hi (dbl-buf)
__device__ __nv_bfloat16 g_ha_lo[2][BATCH * HID];  // h state split lo
__device__ __nv_bfloat16 g_Whi[HID * HID];         // W_h2h hi, [n][k]
__device__ __nv_bfloat16 g_Wlo[HID * HID];         // W_h2h lo
__device__ __nv_bfloat16 g_Wihi[HID * IN_F];       // W_i2h hi, [n][k]
__device__ __nv_bfloat16 g_Wilo[HID * IN_F];       // W_i2h lo
__device__ __nv_bfloat16 g_Wohi[OUT_F * HID];      // W_h2o hi, [n][k]
__device__ __nv_bfloat16 g_Wolo[OUT_F * HID];      // W_h2o lo

__device__ __forceinline__ uint32_t pack2(__nv_bfloat16 a, __nv_bfloat16 b) {
    __nv_bfloat162 t; t.x = a; t.y = b;
    return *(uint32_t*)&t;
}
__device__ __forceinline__ uint32_t smem_u32(const void* p) {
    uint32_t a;
    asm("{ .reg .u64 t; cvta.to.shared.u64 t, %1; cvt.u32.u64 %0, t; }"
        : "=r"(a) : "l"(p));
    return a;
}
__device__ __forceinline__ float tanh_ap(float x) {
    float y;
    asm("tanh.approx.f32 %0, %1;" : "=f"(y) : "f"(x));
    return y;
}
__device__ __forceinline__ void split_store(__nv_bfloat16* hiDst,
                                            __nv_bfloat16* loDst, float4 v) {
    __nv_bfloat16 hx = __float2bfloat16(v.x);
    __nv_bfloat16 hy = __float2bfloat16(v.y);
    __nv_bfloat16 hz = __float2bfloat16(v.z);
    __nv_bfloat16 hw = __float2bfloat16(v.w);
    uint2 hv, lv;
    hv.x = pack2(hx, hy); hv.y = pack2(hz, hw);
    lv.x = pack2(__float2bfloat16(v.x - __bfloat162float(hx)),
                 __float2bfloat16(v.y - __bfloat162float(hy)));
    lv.y = pack2(__float2bfloat16(v.z - __bfloat162float(hz)),
                 __float2bfloat16(v.w - __bfloat162float(hw)));
    *(uint2*)hiDst = hv;
    *(uint2*)loDst = lv;
}

#define CLUSTER_SYNC() do { \
    asm volatile("barrier.cluster.arrive.aligned;" ::: "memory"); \
    asm volatile("barrier.cluster.wait.aligned;" ::: "memory"); \
} while (0)

#define CP_ASYNC16(dst, src) \
    asm volatile("cp.async.cg.shared.global [%0], [%1], 16;" \
                 :: "r"(dst), "l"(src) : "memory")
#define CP_COMMIT() asm volatile("cp.async.commit_group;" ::: "memory")
#define CP_WAIT0()  asm volatile("cp.async.wait_group 0;" ::: "memory")

// mma.sync m16n8k16 bf16 (baseline ISA)
#define MMA16816(c, a, b) \
    asm volatile("mma.sync.aligned.m16n8k16.row.col.f32.bf16.bf16.f32 " \
        "{%0,%1,%2,%3}, {%4,%5,%6,%7}, {%8,%9}, {%0,%1,%2,%3};" \
        : "+f"((c)[0]), "+f"((c)[1]), "+f"((c)[2]), "+f"((c)[3]) \
        : "r"((a)[0]), "r"((a)[1]), "r"((a)[2]), "r"((a)[3]), \
          "r"((b)[0]), "r"((b)[1]))

#define LDSM4(r, addr) \
    asm volatile("ldmatrix.sync.aligned.m8n8.x4.shared.b16 {%0,%1,%2,%3}, [%4];" \
        : "=r"((r)[0]), "=r"((r)[1]), "=r"((r)[2]), "=r"((r)[3]) : "r"(addr))

// ============================================================================
// prep kernels: split fp32 weights / initial h into bf16 hi/lo globals.
// ============================================================================
__global__ void prep_w(const float* __restrict__ W)
{
    int idx = blockIdx.x * 256 + threadIdx.x;
    float v = W[idx];
    __nv_bfloat16 hi = __float2bfloat16(v);
    g_Whi[idx] = hi;
    g_Wlo[idx] = __float2bfloat16(v - __bfloat162float(hi));
}
__global__ void prep_wi(const float* __restrict__ W)
{
    int idx = blockIdx.x * 256 + threadIdx.x;
    float v = W[idx];
    __nv_bfloat16 hi = __float2bfloat16(v);
    g_Wihi[idx] = hi;
    g_Wilo[idx] = __float2bfloat16(v - __bfloat162float(hi));
}
__global__ void prep_wo(const float* __restrict__ W)
{
    int idx = blockIdx.x * 256 + threadIdx.x;
    float v = W[idx];
    __nv_bfloat16 hi = __float2bfloat16(v);
    g_Wohi[idx] = hi;
    g_Wolo[idx] = __float2bfloat16(v - __bfloat162float(hi));
}
// split hc1 -> g_ha[1] (buffer read at t=0)
__global__ void prep_h(const float* __restrict__ hc1)
{
    int i = (blockIdx.x * 256 + threadIdx.x) * 4;
    float4 v = *(const float4*)(hc1 + i);
    split_store(&g_ha_hi[1][i], &g_ha_lo[1][i], v);
}

// ============================================================================
// step_fused: ALL 16 recurrence steps, persistent, 2-CTA clusters.
// 512 threads = 16 warps (4m x 4n), warp tile 32m x 32n.
// A arrives as pre-split bf16 (g_ha) via cp.async double-buffered chunks;
// epilogue splits h_new and writes bf16 hi/lo back (producer-side split).
// ============================================================================
#define WPITCH 264
#define APITCH 72
#define W_HALF_ELEMS (128 * WPITCH)
#define A_HL_ELEMS   (128 * APITCH)
#define A_BUF_ELEMS  (2 * A_HL_ELEMS)
#define A_BASE_ELEMS (2 * W_HALF_ELEMS)
#define STEP_SMEM ((A_BASE_ELEMS + 2 * A_BUF_ELEMS) * 2)

__global__ __launch_bounds__(512, 1) __cluster_dims__(2, 1, 1)
void step_fused(const float* __restrict__ bias,
                const float* __restrict__ i2h_seq,
                float* __restrict__ h2h_seq,
                float* __restrict__ hc1f)
{
    extern __shared__ __nv_bfloat16 sm[];
    __nv_bfloat16* sWhi = sm;
    __nv_bfloat16* sWlo = sm + W_HALF_ELEMS;

    const int tid = threadIdx.x;
    const int bid = blockIdx.x;
    const int n0 = (bid & 1) * 128;
    const int m0 = (bid >> 1) * 128;

    // ---- load W half ONCE (covers all 16 steps) ----
    #pragma unroll
    for (int i = tid; i < 4096; i += 512) {
        int n = i >> 5;
        int k8 = (i & 31) * 8;
        *(uint4*)(sWhi + n * WPITCH + k8) =
            *(const uint4*)(g_Whi + (size_t)(n0 + n) * HID + k8);
        *(uint4*)(sWlo + n * WPITCH + k8) =
            *(const uint4*)(g_Wlo + (size_t)(n0 + n) * HID + k8);
    }

    const int w = tid >> 5, lane = tid & 31;
    const int mwb = (w >> 2) * 32;
    const int nwb = (w & 3) * 32;
    const int tq = lane >> 2, tr = lane & 3;
    const int quad = lane >> 3, rl = lane & 7;

    uint32_t a_off[2], b_off[2];
    #pragma unroll
    for (int mb = 0; mb < 2; mb++)
        a_off[mb] = (uint32_t)(((mwb + mb * 16 + rl + (quad & 1) * 8) * APITCH
                                + (quad >> 1) * 8) * 2);
    #pragma unroll
    for (int nbp = 0; nbp < 2; nbp++)
        b_off[nbp] = (uint32_t)(((nwb + (nbp * 2 + (quad >> 1)) * 8 + rl) * WPITCH
                                 + (quad & 1) * 8) * 2);

    const uint32_t smb  = smem_u32(sm);
    const uint32_t wHiB = smb;
    const uint32_t wLoB = smb + W_HALF_ELEMS * 2;
    const uint32_t aB   = smb + A_BASE_ELEMS * 2;

    for (int t = 0; t < T_STEPS; t++) {
        const __nv_bfloat16* __restrict__ Ahi = g_ha_hi[(t + 1) & 1];
        const __nv_bfloat16* __restrict__ Alo = g_ha_lo[(t + 1) & 1];
        __nv_bfloat16* __restrict__ HhiO = g_ha_hi[t & 1];
        __nv_bfloat16* __restrict__ HloO = g_ha_lo[t & 1];
        const float* __restrict__ i2h_t = i2h_seq + (size_t)t * SZ_HC;
        float* __restrict__ h2h_out = h2h_seq + (size_t)t * SZ_HC;

        float acc[2][4][4];
        #pragma unroll
        for (int mb = 0; mb < 2; mb++)
            #pragma unroll
            for (int nb = 0; nb < 4; nb++)
                #pragma unroll
                for (int q = 0; q < 4; q++) acc[mb][nb][q] = 0.f;

        // issue chunk 0 copy (buffer 0)
        #pragma unroll
        for (int it = 0; it < 4; it++) {
            int cid = tid + it * 512;
            int half = cid >> 10;
            int r = (cid >> 3) & 127;
            int seg = cid & 7;
            const __nv_bfloat16* src =
                (half ? Alo : Ahi) + (size_t)(m0 + r) * HID + seg * 8;
            uint32_t dst = aB + half * (A_HL_ELEMS * 2)
                         + (uint32_t)(r * APITCH + seg * 8) * 2;
            CP_ASYNC16(dst, src);
        }
        CP_COMMIT();

        for (int c = 0; c < 4; c++) {
            const int cur = c & 1, nxt = cur ^ 1;

            CP_WAIT0();
            __syncthreads();

            if (c < 3) {
                #pragma unroll
                for (int it = 0; it < 4; it++) {
                    int cid = tid + it * 512;
                    int half = cid >> 10;
                    int r = (cid >> 3) & 127;
                    int seg = cid & 7;
                    const __nv_bfloat16* src =
                        (half ? Alo : Ahi) + (size_t)(m0 + r) * HID
                        + (c + 1) * 64 + seg * 8;
                    uint32_t dst = aB + nxt * (A_BUF_ELEMS * 2)
                                 + half * (A_HL_ELEMS * 2)
                                 + (uint32_t)(r * APITCH + seg * 8) * 2;
                    CP_ASYNC16(dst, src);
                }
                CP_COMMIT();
            }

            const uint32_t aHi = aB + cur * (A_BUF_ELEMS * 2);
            const uint32_t aLo = aHi + A_HL_ELEMS * 2;
            #pragma unroll
            for (int kk = 0; kk < 64; kk += 16) {
                uint32_t ah[2][4], al[2][4], bh[2][4], bl[2][4];
                #pragma unroll
                for (int mb = 0; mb < 2; mb++) {
                    LDSM4(ah[mb], aHi + a_off[mb] + kk * 2);
                    LDSM4(al[mb], aLo + a_off[mb] + kk * 2);
                }
                const uint32_t kb = (c * 64 + kk) * 2;
                #pragma unroll
                for (int nbp = 0; nbp < 2; nbp++) {
                    LDSM4(bh[nbp], wHiB + b_off[nbp] + kb);
                    LDSM4(bl[nbp], wLoB + b_off[nbp] + kb);
                }
                #pragma unroll
                for (int nb = 0; nb < 4; nb++)
                    #pragma unroll
                    for (int mb = 0; mb < 2; mb++)
                        MMA16816(acc[mb][nb], ah[mb], &bh[nb >> 1][(nb & 1) * 2]);
                #pragma unroll
                for (int nb = 0; nb < 4; nb++)
                    #pragma unroll
                    for (int mb = 0; mb < 2; mb++)
                        MMA16816(acc[mb][nb], ah[mb], &bl[nb >> 1][(nb & 1) * 2]);
                #pragma unroll
                for (int nb = 0; nb < 4; nb++)
                    #pragma unroll
                    for (int mb = 0; mb < 2; mb++)
                        MMA16816(acc[mb][nb], al[mb], &bh[nb >> 1][(nb & 1) * 2]);
            }
        }

        // ---- epilogue: bias, h2h write, tanh, producer-side h split ----
        #pragma unroll
        for (int mb = 0; mb < 2; mb++) {
            #pragma unroll
            for (int nb = 0; nb < 4; nb++) {
                int gr = m0 + mwb + mb * 16 + tq;
                int gc = n0 + nwb + nb * 8 + tr * 2;
                float2 bv = *(const float2*)(bias + gc);
                #pragma unroll
                for (int half = 0; half < 2; half++) {
                    int r = gr + half * 8;
                    float p0 = acc[mb][nb][half * 2 + 0] + bv.x;
                    float p1 = acc[mb][nb][half * 2 + 1] + bv.y;
                    size_t off = (size_t)r * HID + gc;
                    *(float2*)(h2h_out + off) = make_float2(p0, p1);
                    float2 iv = *(const float2*)(i2h_t + off);
                    float h0 = tanh_ap(iv.x + p0);
                    float h1 = tanh_ap(iv.y + p1);
                    __nv_bfloat16 b0 = __float2bfloat16(h0);
                    __nv_bfloat16 b1 = __float2bfloat16(h1);
                    *(uint32_t*)(HhiO + off) = pack2(b0, b1);
                    *(uint32_t*)(HloO + off) =
                        pack2(__float2bfloat16(h0 - __bfloat162float(b0)),
                              __float2bfloat16(h1 - __bfloat162float(b1)));
                    if (t == T_STEPS - 1)
                        *(float2*)(hc1f + off) = make_float2(h0, h1);
                }
            }
        }

        if (t < T_STEPS - 1) CLUSTER_SYNC();
    }
}

// ============================================================================
// i2h_mma: C = X @ W_i2h^T + b.  (unchanged; 2 CTAs/SM)
// ============================================================================
#define IAP 72
#define I2H_SMEM (4 * 128 * IAP * 2)

__global__ __launch_bounds__(256, 2)
void i2h_mma(const float* __restrict__ X,
             const float* __restrict__ bias,
             float* __restrict__ C)
{
    extern __shared__ __nv_bfloat16 ism[];
    __nv_bfloat16* sWhi = ism;
    __nv_bfloat16* sWlo = sWhi + 128 * IAP;
    __nv_bfloat16* sAhi = sWlo + 128 * IAP;
    __nv_bfloat16* sAlo = sAhi + 128 * IAP;

    const int tid = threadIdx.x;
    const int n0 = blockIdx.x * 128;
    const int m0 = blockIdx.y * 128;

    #pragma unroll
    for (int i = tid; i < 1024; i += 256) {
        int n = i >> 3, k8 = (i & 7) * 8;
        *(uint4*)(sWhi + n * IAP + k8) =
            *(const uint4*)(g_Wihi + (size_t)(n0 + n) * IN_F + k8);
        *(uint4*)(sWlo + n * IAP + k8) =
            *(const uint4*)(g_Wilo + (size_t)(n0 + n) * IN_F + k8);
    }
    #pragma unroll
    for (int it = 0; it < 8; it++) {
        int idx = tid + it * 256;
        int m = idx >> 4, kq = (idx & 15) * 4;
        float4 v = *(const float4*)(X + (size_t)(m0 + m) * IN_F + kq);
        split_store(sAhi + m * IAP + kq, sAlo + m * IAP + kq, v);
    }
    __syncthreads();

    const int w = tid >> 5, lane = tid & 31;
    const int mwb = (w >> 1) * 32;
    const int nwb = (w & 1) * 64;
    const int tq = lane >> 2, tr = lane & 3;
    const int quad = lane >> 3, rl = lane & 7;

    uint32_t a_off[2], b_off[4];
    #pragma unroll
    for (int mb = 0; mb < 2; mb++)
        a_off[mb] = (uint32_t)(((mwb + mb * 16 + rl + (quad & 1) * 8) * IAP
                                + (quad >> 1) * 8) * 2);
    #pragma unroll
    for (int nbp = 0; nbp < 4; nbp++)
        b_off[nbp] = (uint32_t)(((nwb + (nbp * 2 + (quad >> 1)) * 8 + rl) * IAP
                                 + (quad & 1) * 8) * 2);

    const uint32_t smb = smem_u32(ism);
    const uint32_t wHiB = smb;
    const uint32_t wLoB = smb + 128 * IAP * 2;
    const uint32_t aHiB = smb + 2 * 128 * IAP * 2;
    const uint32_t aLoB = smb + 3 * 128 * IAP * 2;

    float acc[2][8][4];
    #pragma unroll
    for (int mb = 0; mb < 2; mb++)
        #pragma unroll
        for (int nb = 0; nb < 8; nb++)
            #pragma unroll
            for (int q = 0; q < 4; q++) acc[mb][nb][q] = 0.f;

    #pragma unroll
    for (int kk = 0; kk < 64; kk += 16) {
        uint32_t ah[2][4], al[2][4], bh[4][4], bl[4][4];
        #pragma unroll
        for (int mb = 0; mb < 2; mb++) {
            LDSM4(ah[mb], aHiB + a_off[mb] + kk * 2);
            LDSM4(al[mb], aLoB + a_off[mb] + kk * 2);
        }
        #pragma unroll
        for (int nbp = 0; nbp < 4; nbp++) {
            LDSM4(bh[nbp], wHiB + b_off[nbp] + kk * 2);
            LDSM4(bl[nbp], wLoB + b_off[nbp] + kk * 2);
        }
        #pragma unroll
        for (int nb = 0; nb < 8; nb++)
            #pragma unroll
            for (int mb = 0; mb < 2; mb++)
                MMA16816(acc[mb][nb], ah[mb], &bh[nb >> 1][(nb & 1) * 2]);
        #pragma unroll
        for (int nb = 0; nb < 8; nb++)
            #pragma unroll
            for (int mb = 0; mb < 2; mb++)
                MMA16816(acc[mb][nb], ah[mb], &bl[nb >> 1][(nb & 1) * 2]);
        #pragma unroll
        for (int nb = 0; nb < 8; nb++)
            #pragma unroll
            for (int mb = 0; mb < 2; mb++)
                MMA16816(acc[mb][nb], al[mb], &bh[nb >> 1][(nb & 1) * 2]);
    }

    #pragma unroll
    for (int mb = 0; mb < 2; mb++) {
        #pragma unroll
        for (int nb = 0; nb < 8; nb++) {
            int gr = m0 + mwb + mb * 16 + tq;
            int gc = n0 + nwb + nb * 8 + tr * 2;
            float2 bv = *(const float2*)(bias + gc);
            #pragma unroll
            for (int half = 0; half < 2; half++) {
                size_t off = (size_t)(gr + half * 8) * HID + gc;
                *(float2*)(C + off) =
                    make_float2(acc[mb][nb][half * 2 + 0] + bv.x,
                                acc[mb][nb][half * 2 + 1] + bv.y);
            }
        }
    }
}

// ============================================================================
// head_mma: 512 threads (16 warps, 4m x 4n; warp 32m x 16n).
// A = tanh(i2h+h2h) split on the fly, double-buffered k=64 chunks.
// ============================================================================
#define HWP 264
#define HAP 72
#define HW_ELEMS (64 * HWP)
#define HA_HL   (128 * HAP)
#define HA_BUF  (2 * HA_HL)
#define HA_BASE (2 * HW_ELEMS)
#define HEAD_SMEM ((HA_BASE + 2 * HA_BUF) * 2)

__global__ __launch_bounds__(512, 1)
void head_mma(const float* __restrict__ i2h, const float* __restrict__ h2h,
              const float* __restrict__ bo,
              const float* __restrict__ Wf, const float* __restrict__ bf,
              float* __restrict__ outseq)
{
    extern __shared__ __nv_bfloat16 hsm[];
    __nv_bfloat16* sWhi = hsm;
    __nv_bfloat16* sWlo = hsm + HW_ELEMS;
    __nv_bfloat16* sA   = hsm + HA_BASE;
    __shared__ float wf[NCLS * OUT_F];
    __shared__ float bfs[NCLS];

    const int tid = threadIdx.x;
    const int m0 = blockIdx.x * 128;

    wf[tid] = Wf[tid];
    if (tid < NCLS) bfs[tid] = bf[tid];

    #pragma unroll
    for (int i = tid; i < 2048; i += 512) {
        int n = i >> 5, k8 = (i & 31) * 8;
        *(uint4*)(sWhi + n * HWP + k8) =
            *(const uint4*)(g_Wohi + (size_t)n * HID + k8);
        *(uint4*)(sWlo + n * HWP + k8) =
            *(const uint4*)(g_Wolo + (size_t)n * HID + k8);
    }

    const int w = tid >> 5, lane = tid & 31;
    const int mwb = (w >> 2) * 32;
    const int nwb = (w & 3) * 16;
    const int tq = lane >> 2, tr = lane & 3;
    const int quad = lane >> 3, rl = lane & 7;

    uint32_t a_off[2];
    #pragma unroll
    for (int mb = 0; mb < 2; mb++)
        a_off[mb] = (uint32_t)(((mwb + mb * 16 + rl + (quad & 1) * 8) * HAP
                                + (quad >> 1) * 8) * 2);
    uint32_t b_off = (uint32_t)(((nwb + (quad >> 1) * 8 + rl) * HWP
                                 + (quad & 1) * 8) * 2);

    const uint32_t smb = smem_u32(hsm);
    const uint32_t wHiB = smb;
    const uint32_t wLoB = smb + HW_ELEMS * 2;
    const uint32_t aB   = smb + HA_BASE * 2;

    float acc[2][2][4];
    #pragma unroll
    for (int mb = 0; mb < 2; mb++)
        #pragma unroll
        for (int nb = 0; nb < 2; nb++)
            #pragma unroll
            for (int q = 0; q < 4; q++) acc[mb][nb][q] = 0.f;

    float4 pfi[4], pfh[4];
    #pragma unroll
    for (int it = 0; it < 4; it++) {
        int idx = tid + it * 512;
        int m = idx >> 4, kq = (idx & 15) * 4;
        size_t off = (size_t)(m0 + m) * HID + kq;
        pfi[it] = *(const float4*)(i2h + off);
        pfh[it] = *(const float4*)(h2h + off);
    }
    #pragma unroll
    for (int it = 0; it < 4; it++) {
        int idx = tid + it * 512;
        int m = idx >> 4, kq = (idx & 15) * 4;
        float4 v;
        v.x = tanh_ap(pfi[it].x + pfh[it].x);
        v.y = tanh_ap(pfi[it].y + pfh[it].y);
        v.z = tanh_ap(pfi[it].z + pfh[it].z);
        v.w = tanh_ap(pfi[it].w + pfh[it].w);
        split_store(sA + m * HAP + kq, sA + HA_HL + m * HAP + kq, v);
    }
    __syncthreads();

    for (int c = 0; c < 4; c++) {
        const int cur = c & 1, nxt = cur ^ 1;

        if (c < 3) {
            #pragma unroll
            for (int it = 0; it < 4; it++) {
                int idx = tid + it * 512;
                int m = idx >> 4, kq = (idx & 15) * 4;
                size_t off = (size_t)(m0 + m) * HID + (c + 1) * 64 + kq;
                pfi[it] = *(const float4*)(i2h + off);
                pfh[it] = *(const float4*)(h2h + off);
            }
        }

        const uint32_t aHi = aB + cur * (HA_BUF * 2);
        const uint32_t aLo = aHi + HA_HL * 2;
        #pragma unroll
        for (int kk = 0; kk < 64; kk += 16) {
            uint32_t ah[2][4], al[2][4], bh[4], bl[4];
            #pragma unroll
            for (int mb = 0; mb < 2; mb++) {
                LDSM4(ah[mb], aHi + a_off[mb] + kk * 2);
                LDSM4(al[mb], aLo + a_off[mb] + kk * 2);
            }
            const uint32_t kb = (c * 64 + kk) * 2;
            LDSM4(bh, wHiB + b_off + kb);
            LDSM4(bl, wLoB + b_off + kb);
            #pragma unroll
            for (int nb = 0; nb < 2; nb++)
                #pragma unroll
                for (int mb = 0; mb < 2; mb++)
                    MMA16816(acc[mb][nb], ah[mb], &bh[nb * 2]);
            #pragma unroll
            for (int nb = 0; nb < 2; nb++)
                #pragma unroll
                for (int mb = 0; mb < 2; mb++)
                    MMA16816(acc[mb][nb], ah[mb], &bl[nb * 2]);
            #pragma unroll
            for (int nb = 0; nb < 2; nb++)
                #pragma unroll
                for (int mb = 0; mb < 2; mb++)
                    MMA16816(acc[mb][nb], al[mb], &bh[nb * 2]);
        }

        if (c < 3) {
            #pragma unroll
            for (int it = 0; it < 4; it++) {
                int idx = tid + it * 512;
                int m = idx >> 4, kq = (idx & 15) * 4;
                float4 v;
                v.x = tanh_ap(pfi[it].x + pfh[it].x);
                v.y = tanh_ap(pfi[it].y + pfh[it].y);
                v.z = tanh_ap(pfi[it].z + pfh[it].z);
                v.w = tanh_ap(pfi[it].w + pfh[it].w);
                split_store(sA + nxt * HA_BUF + m * HAP + kq,
                            sA + nxt * HA_BUF + HA_HL + m * HAP + kq, v);
            }
            __syncthreads();
        }
    }

    __syncthreads();
    float* Osm = (float*)sA;
    #pragma unroll
    for (int mb = 0; mb < 2; mb++) {
        #pragma unroll
        for (int nb = 0; nb < 2; nb++) {
            int lr = mwb + mb * 16 + tq;
            int gc = nwb + nb * 8 + tr * 2;
            float2 bv = *(const float2*)(bo + gc);
            #pragma unroll
            for (int half = 0; half < 2; half++) {
                *(float2*)(Osm + (lr + half * 8) * 68 + gc) =
                    make_float2(tanh_ap(acc[mb][nb][half * 2 + 0] + bv.x),
                                tanh_ap(acc[mb][nb][half * 2 + 1] + bv.y));
            }
        }
    }
    __syncthreads();

    #pragma unroll
    for (int i = 0; i < 2; i++) {
        int idx = tid + i * 512;
        int row = idx >> 3;
        int cc  = idx & 7;
        const float* orow = Osm + row * 68;
        const float* wr   = wf + cc * OUT_F;
        float s = bfs[cc];
        #pragma unroll
        for (int o = 0; o < OUT_F; o++) s += orow[o] * wr[o];
        outseq[(size_t)(m0 + row) * NCLS + cc] = s;
    }
}

// ============================================================================
extern "C" void kernel_launch(void* const* d_in, const int* in_sizes, int n_in,
                              void* d_out, int out_size)
{
    const float* x      = (const float*)d_in[0];
    const float* hc1    = (const float*)d_in[2];
    const float* hc2    = (const float*)d_in[3];
    const float* hc3    = (const float*)d_in[4];
    const float* hc4    = (const float*)d_in[5];
    const float* W_i2h  = (const float*)d_in[6];
    const float* b_i2h  = (const float*)d_in[7];
    const float* W_h2h  = (const float*)d_in[8];
    const float* b_h2h  = (const float*)d_in[9];
    const float* W_h2o  = (const float*)d_in[10];
    const float* b_h2o  = (const float*)d_in[11];
    const float* W_fcc  = (const float*)d_in[12];
    const float* b_fcc  = (const float*)d_in[13];

    float* out = (float*)d_out;
    float* i2h_seq = out + OFF_I2H;
    float* h2h_seq = out + OFF_H2H;

    cudaFuncSetAttribute(step_fused, cudaFuncAttributeMaxDynamicSharedMemorySize,
                         STEP_SMEM);
    cudaFuncSetAttribute(i2h_mma, cudaFuncAttributeMaxDynamicSharedMemorySize,
                         I2H_SMEM);
    cudaFuncSetAttribute(head_mma, cudaFuncAttributeMaxDynamicSharedMemorySize,
                         HEAD_SMEM);

    cudaMemcpyAsync(out + OFF_HC2, hc2, (size_t)SZ_HC * sizeof(float),
                    cudaMemcpyDeviceToDevice);
    cudaMemcpyAsync(out + OFF_HC3, hc3, (size_t)SZ_HC * sizeof(float),
                    cudaMemcpyDeviceToDevice);
    cudaMemcpyAsync(out + OFF_HC4, hc4, (size_t)SZ_HC * sizeof(float),
                    cudaMemcpyDeviceToDevice);

    // 0) split weights + initial hidden state into bf16 hi/lo
    prep_w<<<256, 256>>>(W_h2h);
    prep_wi<<<64, 256>>>(W_i2h);
    prep_wo<<<64, 256>>>(W_h2o);
    prep_h<<<2048, 256>>>(hc1);

    // 1) i2h over all timesteps (tensor cores, 2 CTAs/SM)
    dim3 g1(2, (T_STEPS * BATCH) / 128);
    i2h_mma<<<g1, 256, I2H_SMEM>>>(x, b_i2h, i2h_seq);

    // 2) ALL 16 recurrence steps: persistent, clusters, cp.async A feed
    step_fused<<<STEP_CTAS, 512, STEP_SMEM>>>(
        b_h2h, i2h_seq, h2h_seq, out + OFF_HC1);

    // 3) output head (512 threads, tensor cores + fused fcc)
    head_mma<<<(T_STEPS * BATCH) / 128, 512, HEAD_SMEM>>>(
        i2h_seq, h2h_seq, b_h2o, W_fcc, b_fcc, out + OFF_OUTSEQ);
}